// round 3
// baseline (speedup 1.0000x reference)
#include <cuda_runtime.h>
#include <math.h>

#define D_MODEL 1024
#define NHEADS  16
#define HDIM    64
#define HALF    32
#define BB      2
#define SS      2048
#define MTOK    (BB*SS)          // 4096 tokens

// Scratch (static __device__ arrays — no allocations allowed)
__device__ float g_qkv[MTOK * 3 * D_MODEL];   // [4096][3072]
__device__ float g_q[MTOK * D_MODEL];         // [B*H][S][64]
__device__ float g_k[MTOK * D_MODEL];
__device__ float g_v[MTOK * D_MODEL];
__device__ float g_attn[MTOK * D_MODEL];      // [4096][1024] attention output

// ---------------------------------------------------------------------------
// GEMM: C[M,N] = A[M,K] @ W[N,K]^T + bias[N]
// 128x128 tile, BK=16, 256 threads, 8x8 microtile.
// ---------------------------------------------------------------------------
#define GBM 128
#define GBN 128
#define GBK 16

__global__ void __launch_bounds__(256)
gemm_tn_bias(const float* __restrict__ A, const float* __restrict__ W,
             const float* __restrict__ bias, float* __restrict__ C,
             int M, int N, int K)
{
    __shared__ float As[GBK][GBM];
    __shared__ float Bs[GBK][GBN];
    const int tid = threadIdx.x;
    const int tx  = tid & 15;          // 16 col groups
    const int ty  = tid >> 4;          // 16 row groups
    const int row0 = blockIdx.y * GBM;
    const int col0 = blockIdx.x * GBN;

    float acc[8][8];
#pragma unroll
    for (int i = 0; i < 8; i++)
#pragma unroll
        for (int j = 0; j < 8; j++) acc[i][j] = 0.f;

    for (int k0 = 0; k0 < K; k0 += GBK) {
#pragma unroll
        for (int i = 0; i < 2; i++) {
            int j  = tid + i * 256;            // 0..511 float4 slots
            int r  = j >> 2;                   // 0..127
            int kq = (j & 3) << 2;             // 0,4,8,12
            float4 a4 = *(const float4*)(A + (size_t)(row0 + r) * K + k0 + kq);
            As[kq + 0][r] = a4.x; As[kq + 1][r] = a4.y;
            As[kq + 2][r] = a4.z; As[kq + 3][r] = a4.w;
            float4 b4 = *(const float4*)(W + (size_t)(col0 + r) * K + k0 + kq);
            Bs[kq + 0][r] = b4.x; Bs[kq + 1][r] = b4.y;
            Bs[kq + 2][r] = b4.z; Bs[kq + 3][r] = b4.w;
        }
        __syncthreads();
#pragma unroll
        for (int kk = 0; kk < GBK; kk++) {
            float af[8], bf[8];
            *(float4*)&af[0] = *(const float4*)&As[kk][ty * 8];
            *(float4*)&af[4] = *(const float4*)&As[kk][ty * 8 + 4];
            *(float4*)&bf[0] = *(const float4*)&Bs[kk][tx * 8];
            *(float4*)&bf[4] = *(const float4*)&Bs[kk][tx * 8 + 4];
#pragma unroll
            for (int i = 0; i < 8; i++)
#pragma unroll
                for (int j = 0; j < 8; j++)
                    acc[i][j] += af[i] * bf[j];
        }
        __syncthreads();
    }
#pragma unroll
    for (int i = 0; i < 8; i++) {
        int rr = row0 + ty * 8 + i;
#pragma unroll
        for (int j = 0; j < 8; j += 4) {
            int cc = col0 + tx * 8 + j;
            float4 o;
            o.x = acc[i][j + 0] + bias[cc + 0];
            o.y = acc[i][j + 1] + bias[cc + 1];
            o.z = acc[i][j + 2] + bias[cc + 2];
            o.w = acc[i][j + 3] + bias[cc + 3];
            *(float4*)(C + (size_t)rr * N + cc) = o;
        }
    }
}

// ---------------------------------------------------------------------------
// RoPE + split/transpose: qkv[4096][3072] -> g_q/g_k (roped), g_v
// Layout out: [B*H][S][64]. Angles computed in fp64 to track the reference's
// fp32 angles to within the reference's own rounding.
// ---------------------------------------------------------------------------
__global__ void rope_split_kernel()
{
    int idx = blockIdx.x * 256 + threadIdx.x;    // (((b*S+s)*H)+h)*64+d
    int d = idx & (HDIM - 1);
    int h = (idx >> 6) & (NHEADS - 1);
    int s = (idx >> 10) & (SS - 1);
    int b = idx >> 21;
    const float* base = g_qkv + (size_t)(b * SS + s) * (3 * D_MODEL);
    int off = h * HDIM;
    int dp = d & (HALF - 1);
    double inv = pow(10000.0, -((double)dp) / (double)HALF);
    double ang = (double)s * inv;
    double csd, snd;
    sincos(ang, &snd, &csd);
    float cs = (float)csd, sn = (float)snd;
    float q1 = base[off + dp],            q2 = base[off + dp + HALF];
    float k1 = base[D_MODEL + off + dp],  k2 = base[D_MODEL + off + dp + HALF];
    float qo, ko;
    if (d < HALF) { qo = q1 * cs - q2 * sn; ko = k1 * cs - k2 * sn; }
    else          { qo = q1 * sn + q2 * cs; ko = k1 * sn + k2 * cs; }
    int o = ((b * NHEADS + h) * SS + s) * HDIM + d;
    g_q[o] = qo;
    g_k[o] = ko;
    g_v[o] = base[2 * D_MODEL + off + d];
}

// ---------------------------------------------------------------------------
// Flash attention (fp32, causal). Block = 64 queries of one (b,h).
// 256 threads: thread (r = tid/4, cg = tid%4) owns row r, 16 cols.
// smem: Qs 16K + Kt/Ps 16K (reused) + Vs 16K = 48KB.
// ---------------------------------------------------------------------------
__global__ void __launch_bounds__(256)
flash_attn_kernel()
{
    __shared__ float Qs[64][HDIM];
    __shared__ float KtPs[64][64];   // phase 1: K^T [d][key]; phase 2: P [q][key]
    __shared__ float Vs[64][HDIM];

    const int tid = threadIdx.x;
    const int r   = tid >> 2;
    const int c0  = (tid & 3) << 4;
    const int bh  = blockIdx.y;
    const int q0  = blockIdx.x * 64;

    const float* Qb = g_q + (size_t)bh * SS * HDIM;
    const float* Kb = g_k + (size_t)bh * SS * HDIM;
    const float* Vb = g_v + (size_t)bh * SS * HDIM;

#pragma unroll
    for (int i = 0; i < 4; i++) {
        int j = tid + i * 256;         // 1024 float4 slots
        int qr = j >> 4, dq = (j & 15) << 2;
        float4 v = *(const float4*)(Qb + (size_t)(q0 + qr) * HDIM + dq);
        v.x *= 0.125f; v.y *= 0.125f; v.z *= 0.125f; v.w *= 0.125f;  // 1/sqrt(64)
        *(float4*)&Qs[qr][dq] = v;
    }

    float o[16];
#pragma unroll
    for (int j = 0; j < 16; j++) o[j] = 0.f;
    float m_run = -INFINITY, l_run = 0.f;

    const int ntiles = (q0 >> 6) + 1;   // causal: only tiles with k0 <= q0
    for (int kt = 0; kt < ntiles; kt++) {
        int k0 = kt * 64;
        __syncthreads();   // guard smem overwrite vs previous iteration / Qs store
#pragma unroll
        for (int i = 0; i < 4; i++) {
            int j = tid + i * 256;
            int key = j >> 4, dq = (j & 15) << 2;
            float4 kv = *(const float4*)(Kb + (size_t)(k0 + key) * HDIM + dq);
            KtPs[dq + 0][key] = kv.x; KtPs[dq + 1][key] = kv.y;
            KtPs[dq + 2][key] = kv.z; KtPs[dq + 3][key] = kv.w;
            *(float4*)&Vs[key][dq] = *(const float4*)(Vb + (size_t)(k0 + key) * HDIM + dq);
        }
        __syncthreads();

        // S = Q K^T  (row r x 16 cols)
        float sc[16];
#pragma unroll
        for (int j = 0; j < 16; j++) sc[j] = 0.f;
#pragma unroll 8
        for (int d = 0; d < HDIM; d++) {
            float qv = Qs[r][d];
            const float4* kp = (const float4*)&KtPs[d][c0];
#pragma unroll
            for (int g = 0; g < 4; g++) {
                float4 k4 = kp[g];
                sc[4 * g + 0] += qv * k4.x;
                sc[4 * g + 1] += qv * k4.y;
                sc[4 * g + 2] += qv * k4.z;
                sc[4 * g + 3] += qv * k4.w;
            }
        }

        if (k0 == q0) {                 // diagonal tile: causal mask
#pragma unroll
            for (int j = 0; j < 16; j++)
                if (k0 + c0 + j > q0 + r) sc[j] = -INFINITY;
        }

        // online softmax: row reduction across 4 threads sharing row r
        float mx = sc[0];
#pragma unroll
        for (int j = 1; j < 16; j++) mx = fmaxf(mx, sc[j]);
        mx = fmaxf(mx, __shfl_xor_sync(0xffffffffu, mx, 1));
        mx = fmaxf(mx, __shfl_xor_sync(0xffffffffu, mx, 2));
        float m_new = fmaxf(m_run, mx);
        float alpha = __expf(m_run - m_new);
        float lsum = 0.f;
#pragma unroll
        for (int j = 0; j < 16; j++) {
            float p = __expf(sc[j] - m_new);
            sc[j] = p;
            lsum += p;
        }
        lsum += __shfl_xor_sync(0xffffffffu, lsum, 1);
        lsum += __shfl_xor_sync(0xffffffffu, lsum, 2);
        l_run = l_run * alpha + lsum;
        m_run = m_new;
#pragma unroll
        for (int j = 0; j < 16; j++) o[j] *= alpha;

        __syncthreads();   // everyone done reading Kt
        *(float4*)&KtPs[r][c0 + 0]  = make_float4(sc[0],  sc[1],  sc[2],  sc[3]);
        *(float4*)&KtPs[r][c0 + 4]  = make_float4(sc[4],  sc[5],  sc[6],  sc[7]);
        *(float4*)&KtPs[r][c0 + 8]  = make_float4(sc[8],  sc[9],  sc[10], sc[11]);
        *(float4*)&KtPs[r][c0 + 12] = make_float4(sc[12], sc[13], sc[14], sc[15]);
        __syncthreads();

        // O += P V   (thread owns row r, output dims c0..c0+15)
#pragma unroll 8
        for (int c = 0; c < 64; c++) {
            float p = KtPs[r][c];
            const float4* vp = (const float4*)&Vs[c][c0];
#pragma unroll
            for (int g = 0; g < 4; g++) {
                float4 v4 = vp[g];
                o[4 * g + 0] += p * v4.x;
                o[4 * g + 1] += p * v4.y;
                o[4 * g + 2] += p * v4.z;
                o[4 * g + 3] += p * v4.w;
            }
        }
    }

    // epilogue: normalize, write to [b*S+q][h*64+d] layout for final GEMM
    float invl = 1.f / l_run;
    int b = bh >> 4, h = bh & 15;
    int qg = q0 + r;
    float* outp = g_attn + (size_t)(b * SS + qg) * D_MODEL + h * HDIM + c0;
#pragma unroll
    for (int j = 0; j < 16; j += 4) {
        *(float4*)(outp + j) = make_float4(o[j] * invl, o[j + 1] * invl,
                                           o[j + 2] * invl, o[j + 3] * invl);
    }
}

// ---------------------------------------------------------------------------
extern "C" void kernel_launch(void* const* d_in, const int* in_sizes, int n_in,
                              void* d_out, int out_size)
{
    // Resolve inputs BY ELEMENT COUNT (all five are pairwise distinct),
    // eliminating any assumption about metadata ordering.
    const float* x     = 0;   // 4194304 = 2*2048*1024
    const float* qkv_w = 0;   // 3145728 = 3072*1024
    const float* qkv_b = 0;   // 3072
    const float* out_w = 0;   // 1048576 = 1024*1024
    const float* out_b = 0;   // 1024
    for (int i = 0; i < n_in; i++) {
        switch (in_sizes[i]) {
            case MTOK * D_MODEL:            x     = (const float*)d_in[i]; break;
            case 3 * D_MODEL * D_MODEL:     qkv_w = (const float*)d_in[i]; break;
            case 3 * D_MODEL:               qkv_b = (const float*)d_in[i]; break;
            case D_MODEL * D_MODEL:         out_w = (const float*)d_in[i]; break;
            case D_MODEL:                   out_b = (const float*)d_in[i]; break;
            default: break;
        }
    }
    float* out = (float*)d_out;

    float *qkv_p, *attn_p;
    cudaGetSymbolAddress((void**)&qkv_p,  g_qkv);
    cudaGetSymbolAddress((void**)&attn_p, g_attn);

    // 1) QKV projection: [4096,1024] @ [3072,1024]^T + b -> [4096,3072]
    gemm_tn_bias<<<dim3((3 * D_MODEL) / GBN, MTOK / GBM), 256>>>(
        x, qkv_w, qkv_b, qkv_p, MTOK, 3 * D_MODEL, D_MODEL);

    // 2) RoPE + split to [B*H][S][64]
    rope_split_kernel<<<(MTOK * D_MODEL) / 256, 256>>>();

    // 3) causal flash attention
    flash_attn_kernel<<<dim3(SS / 64, BB * NHEADS), 256>>>();

    // 4) output projection: [4096,1024] @ [1024,1024]^T + b -> d_out
    gemm_tn_bias<<<dim3(D_MODEL / GBN, MTOK / GBM), 256>>>(
        attn_p, out_w, out_b, out, MTOK, D_MODEL, D_MODEL);
}

// round 4
// speedup vs baseline: 1.8371x; 1.8371x over previous
#include <cuda_runtime.h>
#include <math.h>

#define D_MODEL 1024
#define NHEADS  16
#define HDIM    64
#define HALF    32
#define BB      2
#define SS      2048
#define MTOK    (BB*SS)          // 4096 tokens

// Scratch (static __device__ arrays — no allocations allowed)
__device__ float g_qkv[MTOK * 3 * D_MODEL];   // [4096][3072]
__device__ float g_q[MTOK * D_MODEL];         // [B*H][S][64]
__device__ float g_k[MTOK * D_MODEL];
__device__ float g_v[MTOK * D_MODEL];
__device__ float g_attn[MTOK * D_MODEL];      // [4096][1024]

// ---------------------------------------------------------------------------
// GEMM: C[M,N] = A[M,K] @ W[N,K]^T + bias[N]
// 128x128 tile, BK=16, 256 threads, 8x8 microtile.  (unchanged this round)
// ---------------------------------------------------------------------------
#define GBM 128
#define GBN 128
#define GBK 16

__global__ void __launch_bounds__(256)
gemm_tn_bias(const float* __restrict__ A, const float* __restrict__ W,
             const float* __restrict__ bias, float* __restrict__ C,
             int M, int N, int K)
{
    __shared__ float As[GBK][GBM];
    __shared__ float Bs[GBK][GBN];
    const int tid = threadIdx.x;
    const int tx  = tid & 15;
    const int ty  = tid >> 4;
    const int row0 = blockIdx.y * GBM;
    const int col0 = blockIdx.x * GBN;

    float acc[8][8];
#pragma unroll
    for (int i = 0; i < 8; i++)
#pragma unroll
        for (int j = 0; j < 8; j++) acc[i][j] = 0.f;

    for (int k0 = 0; k0 < K; k0 += GBK) {
#pragma unroll
        for (int i = 0; i < 2; i++) {
            int j  = tid + i * 256;
            int r  = j >> 2;
            int kq = (j & 3) << 2;
            float4 a4 = *(const float4*)(A + (size_t)(row0 + r) * K + k0 + kq);
            As[kq + 0][r] = a4.x; As[kq + 1][r] = a4.y;
            As[kq + 2][r] = a4.z; As[kq + 3][r] = a4.w;
            float4 b4 = *(const float4*)(W + (size_t)(col0 + r) * K + k0 + kq);
            Bs[kq + 0][r] = b4.x; Bs[kq + 1][r] = b4.y;
            Bs[kq + 2][r] = b4.z; Bs[kq + 3][r] = b4.w;
        }
        __syncthreads();
#pragma unroll
        for (int kk = 0; kk < GBK; kk++) {
            float af[8], bf[8];
            *(float4*)&af[0] = *(const float4*)&As[kk][ty * 8];
            *(float4*)&af[4] = *(const float4*)&As[kk][ty * 8 + 4];
            *(float4*)&bf[0] = *(const float4*)&Bs[kk][tx * 8];
            *(float4*)&bf[4] = *(const float4*)&Bs[kk][tx * 8 + 4];
#pragma unroll
            for (int i = 0; i < 8; i++)
#pragma unroll
                for (int j = 0; j < 8; j++)
                    acc[i][j] += af[i] * bf[j];
        }
        __syncthreads();
    }
#pragma unroll
    for (int i = 0; i < 8; i++) {
        int rr = row0 + ty * 8 + i;
#pragma unroll
        for (int j = 0; j < 8; j += 4) {
            int cc = col0 + tx * 8 + j;
            float4 o;
            o.x = acc[i][j + 0] + bias[cc + 0];
            o.y = acc[i][j + 1] + bias[cc + 1];
            o.z = acc[i][j + 2] + bias[cc + 2];
            o.w = acc[i][j + 3] + bias[cc + 3];
            *(float4*)(C + (size_t)rr * N + cc) = o;
        }
    }
}

// ---------------------------------------------------------------------------
// RoPE + split/transpose (unchanged; fp64 angles track reference precision)
// ---------------------------------------------------------------------------
__global__ void rope_split_kernel()
{
    int idx = blockIdx.x * 256 + threadIdx.x;
    int d = idx & (HDIM - 1);
    int h = (idx >> 6) & (NHEADS - 1);
    int s = (idx >> 10) & (SS - 1);
    int b = idx >> 21;
    const float* base = g_qkv + (size_t)(b * SS + s) * (3 * D_MODEL);
    int off = h * HDIM;
    int dp = d & (HALF - 1);
    double inv = pow(10000.0, -((double)dp) / (double)HALF);
    double ang = (double)s * inv;
    double csd, snd;
    sincos(ang, &snd, &csd);
    float cs = (float)csd, sn = (float)snd;
    float q1 = base[off + dp],            q2 = base[off + dp + HALF];
    float k1 = base[D_MODEL + off + dp],  k2 = base[D_MODEL + off + dp + HALF];
    float qo, ko;
    if (d < HALF) { qo = q1 * cs - q2 * sn; ko = k1 * cs - k2 * sn; }
    else          { qo = q1 * sn + q2 * cs; ko = k1 * sn + k2 * cs; }
    int o = ((b * NHEADS + h) * SS + s) * HDIM + d;
    g_q[o] = qo;
    g_k[o] = ko;
    g_v[o] = base[2 * D_MODEL + off + d];
}

// ---------------------------------------------------------------------------
// Flash attention v2: 64x64 tile, 256 threads as 16x16, 4x4 register microtile.
// All smem reads are LDS.128: either broadcast (Q/P rows) or distinct-tx
// (K^T/V cols) -> conflict-free with stride 64, exactly 48KB static smem.
// ---------------------------------------------------------------------------
__global__ void __launch_bounds__(256)
flash_attn_kernel()
{
    __shared__ float Qs[64][64];   // natural [q][d], pre-scaled by 1/sqrt(64)
    __shared__ float KP[64][64];   // phase 1: K^T [d][k]; phase 2: P [q][k]
    __shared__ float Vs[64][64];   // natural [k][d]

    const int tid = threadIdx.x;
    const int ty  = tid >> 4;          // 0..15: q-row group
    const int tx  = tid & 15;          // 0..15: col group
    const int bh  = blockIdx.y;
    const int q0  = blockIdx.x * 64;

    const float* Qb = g_q + (size_t)bh * SS * HDIM;
    const float* Kb = g_k + (size_t)bh * SS * HDIM;
    const float* Vb = g_v + (size_t)bh * SS * HDIM;

    // Q fill (natural layout, coalesced, scaled)
#pragma unroll
    for (int i = 0; i < 4; i++) {
        int j  = tid + i * 256;
        int qr = j >> 4, dq = (j & 15) << 2;
        float4 v = *(const float4*)(Qb + (size_t)(q0 + qr) * HDIM + dq);
        v.x *= 0.125f; v.y *= 0.125f; v.z *= 0.125f; v.w *= 0.125f;
        *(float4*)&Qs[qr][dq] = v;
    }

    float o[16];
#pragma unroll
    for (int j = 0; j < 16; j++) o[j] = 0.f;
    float mrow[4], lrow[4];
#pragma unroll
    for (int i = 0; i < 4; i++) { mrow[i] = -INFINITY; lrow[i] = 0.f; }

    for (int kt = 0; kt <= (int)blockIdx.x; kt++) {
        const int k0 = kt * 64;
        __syncthreads();   // previous phase-2 reads done before refill

        // K fill transposed (k-fast mapping: stride-1 smem stores), V natural
#pragma unroll
        for (int i = 0; i < 4; i++) {
            int j  = tid + i * 256;
            int kq = j & 63, d4 = (j >> 6) << 2;
            float4 kv = *(const float4*)(Kb + (size_t)(k0 + kq) * HDIM + d4);
            KP[d4 + 0][kq] = kv.x; KP[d4 + 1][kq] = kv.y;
            KP[d4 + 2][kq] = kv.z; KP[d4 + 3][kq] = kv.w;
            int key = j >> 4, dq = (j & 15) << 2;
            *(float4*)&Vs[key][dq] =
                *(const float4*)(Vb + (size_t)(k0 + key) * HDIM + dq);
        }
        __syncthreads();

        // ---- S = Q K^T : 4x4 microtile ----
        float sc[16];
#pragma unroll
        for (int j = 0; j < 16; j++) sc[j] = 0.f;
#pragma unroll 2
        for (int d0 = 0; d0 < HDIM; d0 += 4) {
            float4 q4[4], k4[4];
#pragma unroll
            for (int i = 0; i < 4; i++) q4[i] = *(const float4*)&Qs[ty * 4 + i][d0];
#pragma unroll
            for (int t = 0; t < 4; t++) k4[t] = *(const float4*)&KP[d0 + t][tx * 4];
#pragma unroll
            for (int i = 0; i < 4; i++) {
                float qa0 = q4[i].x, qa1 = q4[i].y, qa2 = q4[i].z, qa3 = q4[i].w;
                sc[i*4+0] += qa0*k4[0].x + qa1*k4[1].x + qa2*k4[2].x + qa3*k4[3].x;
                sc[i*4+1] += qa0*k4[0].y + qa1*k4[1].y + qa2*k4[2].y + qa3*k4[3].y;
                sc[i*4+2] += qa0*k4[0].z + qa1*k4[1].z + qa2*k4[2].z + qa3*k4[3].z;
                sc[i*4+3] += qa0*k4[0].w + qa1*k4[1].w + qa2*k4[2].w + qa3*k4[3].w;
            }
        }

        if (kt == (int)blockIdx.x) {        // diagonal tile: causal mask
#pragma unroll
            for (int i = 0; i < 4; i++)
#pragma unroll
                for (int jj = 0; jj < 4; jj++)
                    if (k0 + tx * 4 + jj > q0 + ty * 4 + i)
                        sc[i * 4 + jj] = -INFINITY;
        }

        // ---- online softmax (row reduce across 16 tx threads via shfl) ----
#pragma unroll
        for (int i = 0; i < 4; i++) {
            float mx = fmaxf(fmaxf(sc[i*4+0], sc[i*4+1]),
                             fmaxf(sc[i*4+2], sc[i*4+3]));
            mx = fmaxf(mx, __shfl_xor_sync(0xffffffffu, mx, 1));
            mx = fmaxf(mx, __shfl_xor_sync(0xffffffffu, mx, 2));
            mx = fmaxf(mx, __shfl_xor_sync(0xffffffffu, mx, 4));
            mx = fmaxf(mx, __shfl_xor_sync(0xffffffffu, mx, 8));
            float mn    = fmaxf(mrow[i], mx);
            float alpha = __expf(mrow[i] - mn);
            float ls = 0.f;
#pragma unroll
            for (int jj = 0; jj < 4; jj++) {
                float p = __expf(sc[i * 4 + jj] - mn);
                sc[i * 4 + jj] = p;
                ls += p;
            }
            ls += __shfl_xor_sync(0xffffffffu, ls, 1);
            ls += __shfl_xor_sync(0xffffffffu, ls, 2);
            ls += __shfl_xor_sync(0xffffffffu, ls, 4);
            ls += __shfl_xor_sync(0xffffffffu, ls, 8);
            lrow[i] = lrow[i] * alpha + ls;
            mrow[i] = mn;
#pragma unroll
            for (int jj = 0; jj < 4; jj++) o[i * 4 + jj] *= alpha;
        }

        __syncthreads();   // all reads of K^T done before overwriting with P
#pragma unroll
        for (int i = 0; i < 4; i++)
            *(float4*)&KP[ty * 4 + i][tx * 4] =
                make_float4(sc[i*4+0], sc[i*4+1], sc[i*4+2], sc[i*4+3]);
        __syncthreads();

        // ---- O += P V : 4x4 microtile ----
#pragma unroll 2
        for (int kp = 0; kp < 64; kp += 4) {
            float4 p4[4], v4[4];
#pragma unroll
            for (int i = 0; i < 4; i++) p4[i] = *(const float4*)&KP[ty * 4 + i][kp];
#pragma unroll
            for (int t = 0; t < 4; t++) v4[t] = *(const float4*)&Vs[kp + t][tx * 4];
#pragma unroll
            for (int i = 0; i < 4; i++) {
                float pa0 = p4[i].x, pa1 = p4[i].y, pa2 = p4[i].z, pa3 = p4[i].w;
                o[i*4+0] += pa0*v4[0].x + pa1*v4[1].x + pa2*v4[2].x + pa3*v4[3].x;
                o[i*4+1] += pa0*v4[0].y + pa1*v4[1].y + pa2*v4[2].y + pa3*v4[3].y;
                o[i*4+2] += pa0*v4[0].z + pa1*v4[1].z + pa2*v4[2].z + pa3*v4[3].z;
                o[i*4+3] += pa0*v4[0].w + pa1*v4[1].w + pa2*v4[2].w + pa3*v4[3].w;
            }
        }
    }

    // epilogue: normalize, write [b*S+q][h*64+d]
    const int b = bh >> 4, h = bh & 15;
#pragma unroll
    for (int i = 0; i < 4; i++) {
        float invl = 1.f / lrow[i];
        int row = q0 + ty * 4 + i;
        float* outp = g_attn + (size_t)(b * SS + row) * D_MODEL + h * HDIM + tx * 4;
        *(float4*)outp = make_float4(o[i*4+0] * invl, o[i*4+1] * invl,
                                     o[i*4+2] * invl, o[i*4+3] * invl);
    }
}

// ---------------------------------------------------------------------------
extern "C" void kernel_launch(void* const* d_in, const int* in_sizes, int n_in,
                              void* d_out, int out_size)
{
    // Resolve inputs BY ELEMENT COUNT (pairwise distinct sizes).
    const float* x     = 0;
    const float* qkv_w = 0;
    const float* qkv_b = 0;
    const float* out_w = 0;
    const float* out_b = 0;
    for (int i = 0; i < n_in; i++) {
        switch (in_sizes[i]) {
            case MTOK * D_MODEL:            x     = (const float*)d_in[i]; break;
            case 3 * D_MODEL * D_MODEL:     qkv_w = (const float*)d_in[i]; break;
            case 3 * D_MODEL:               qkv_b = (const float*)d_in[i]; break;
            case D_MODEL * D_MODEL:         out_w = (const float*)d_in[i]; break;
            case D_MODEL:                   out_b = (const float*)d_in[i]; break;
            default: break;
        }
    }
    float* out = (float*)d_out;

    float *qkv_p, *attn_p;
    cudaGetSymbolAddress((void**)&qkv_p,  g_qkv);
    cudaGetSymbolAddress((void**)&attn_p, g_attn);

    gemm_tn_bias<<<dim3((3 * D_MODEL) / GBN, MTOK / GBM), 256>>>(
        x, qkv_w, qkv_b, qkv_p, MTOK, 3 * D_MODEL, D_MODEL);

    rope_split_kernel<<<(MTOK * D_MODEL) / 256, 256>>>();

    flash_attn_kernel<<<dim3(SS / 64, BB * NHEADS), 256>>>();

    gemm_tn_bias<<<dim3(D_MODEL / GBN, MTOK / GBM), 256>>>(
        attn_p, out_w, out_b, out, MTOK, D_MODEL, D_MODEL);
}

// round 6
// speedup vs baseline: 2.3795x; 1.2952x over previous
#include <cuda_runtime.h>
#include <cuda_bf16.h>
#include <math.h>
#include <stdint.h>

#define D_MODEL 1024
#define NHEADS  16
#define HDIM    64
#define HALF    32
#define BB      2
#define SS      2048
#define MTOK    (BB*SS)          // 4096 tokens

// Scratch (static __device__ arrays — no allocations allowed)
__device__ float g_qkv[MTOK * 3 * D_MODEL];   // [4096][3072]
__device__ float g_q[MTOK * D_MODEL];         // [B*H][S][64]
__device__ float g_k[MTOK * D_MODEL];
__device__ float g_v[MTOK * D_MODEL];
__device__ float g_attn[MTOK * D_MODEL];      // [4096][1024]

// ===========================================================================
// Warp-level MMA helpers (compute_103-baseline PTX: ldmatrix + mma.sync bf16)
// ===========================================================================
__device__ __forceinline__ uint32_t smem_u32(const void* p) {
    uint32_t a;
    asm("{ .reg .u64 t; cvta.to.shared.u64 t, %1; cvt.u32.u64 %0, t; }"
        : "=r"(a) : "l"(p));
    return a;
}
__device__ __forceinline__ void ldmx4(uint32_t* r, uint32_t addr) {
    asm volatile("ldmatrix.sync.aligned.m8n8.x4.shared.b16 {%0,%1,%2,%3}, [%4];"
                 : "=r"(r[0]), "=r"(r[1]), "=r"(r[2]), "=r"(r[3]) : "r"(addr));
}
__device__ __forceinline__ void mma16816(float* c, const uint32_t* a,
                                         uint32_t b0, uint32_t b1) {
    asm volatile(
        "mma.sync.aligned.m16n8k16.row.col.f32.bf16.bf16.f32 "
        "{%0,%1,%2,%3}, {%4,%5,%6,%7}, {%8,%9}, {%0,%1,%2,%3};"
        : "+f"(c[0]), "+f"(c[1]), "+f"(c[2]), "+f"(c[3])
        : "r"(a[0]), "r"(a[1]), "r"(a[2]), "r"(a[3]), "r"(b0), "r"(b1));
}
__device__ __forceinline__ uint32_t pack_hi(float x, float y,
                                            float& rx, float& ry) {
    __nv_bfloat16 hx = __float2bfloat16(x);
    __nv_bfloat16 hy = __float2bfloat16(y);
    rx = x - __bfloat162float(hx);
    ry = y - __bfloat162float(hy);
    return ((uint32_t)__bfloat16_as_ushort(hy) << 16) |
           (uint32_t)__bfloat16_as_ushort(hx);
}
__device__ __forceinline__ uint32_t pack_bf(float x, float y) {
    return ((uint32_t)__bfloat16_as_ushort(__float2bfloat16(y)) << 16) |
           (uint32_t)__bfloat16_as_ushort(__float2bfloat16(x));
}

// ===========================================================================
// HMMA split-bf16 GEMM: C[M,N] = A[M,K] @ W[N,K]^T + bias[N]
// 128x128 CTA tile, BK=32, 8 warps (2x4), warp tile 64x32.
// 3-term split: AhBh + AhBl + AlBh (drops AlBl <= 2^-18 relative).
// smem pitch 40 bf16 (80B) -> conflict-free ldmatrix.
// ===========================================================================
#define GP 40   // smem pitch in bf16

__global__ void __launch_bounds__(256, 2)
gemm_mma(const float* __restrict__ A, const float* __restrict__ W,
         const float* __restrict__ bias, float* __restrict__ C,
         int M, int N, int K)
{
    __shared__ __align__(16) __nv_bfloat16 Ah[128 * GP];
    __shared__ __align__(16) __nv_bfloat16 Al[128 * GP];
    __shared__ __align__(16) __nv_bfloat16 Bh[128 * GP];
    __shared__ __align__(16) __nv_bfloat16 Bl[128 * GP];

    const int tid  = threadIdx.x;
    const int wid  = tid >> 5;
    const int lane = tid & 31;
    const int row0 = blockIdx.y * 128;
    const int col0 = blockIdx.x * 128;
    const int wm   = (wid >> 2) * 64;     // warp row offset in tile
    const int wn   = (wid & 3) * 32;      // warp col offset in tile

    const uint32_t sAh = smem_u32(Ah), sAl = smem_u32(Al);
    const uint32_t sBh = smem_u32(Bh), sBl = smem_u32(Bl);

    float acc[4][4][4];
#pragma unroll
    for (int mt = 0; mt < 4; mt++)
#pragma unroll
        for (int nt = 0; nt < 4; nt++)
#pragma unroll
            for (int e = 0; e < 4; e++) acc[mt][nt][e] = 0.f;

    // per-thread fill coordinates: 8 threads per row, float4 each (32 cols)
    const int fr = tid >> 3;            // 0..31 (+32*i)
    const int fc = (tid & 7) << 2;      // 0,4,...,28

    for (int k0 = 0; k0 < K; k0 += 32) {
        __syncthreads();
        // ---- fill Ah/Al and Bh/Bl (128 rows x 32 bf16, hi/lo split) ----
#pragma unroll
        for (int i = 0; i < 4; i++) {
            int r = fr + i * 32;
            float4 a4 = *(const float4*)(A + (size_t)(row0 + r) * K + k0 + fc);
            float lx, ly, lz, lw;
            uint32_t h01 = pack_hi(a4.x, a4.y, lx, ly);
            uint32_t h23 = pack_hi(a4.z, a4.w, lz, lw);
            *(uint2*)&Ah[r * GP + fc] = make_uint2(h01, h23);
            *(uint2*)&Al[r * GP + fc] = make_uint2(pack_bf(lx, ly), pack_bf(lz, lw));

            float4 b4 = *(const float4*)(W + (size_t)(col0 + r) * K + k0 + fc);
            uint32_t g01 = pack_hi(b4.x, b4.y, lx, ly);
            uint32_t g23 = pack_hi(b4.z, b4.w, lz, lw);
            *(uint2*)&Bh[r * GP + fc] = make_uint2(g01, g23);
            *(uint2*)&Bl[r * GP + fc] = make_uint2(pack_bf(lx, ly), pack_bf(lz, lw));
        }
        __syncthreads();

#pragma unroll
        for (int k16 = 0; k16 < 32; k16 += 16) {
            // B fragments: 2 ldmatrix.x4 cover 4 n8-tiles (hi), same for lo
            uint32_t bh[2][4], bl[2][4];
            const uint32_t bln = (lane & 7) + ((lane >> 4) << 3);  // n within 16
            const uint32_t blk = ((lane >> 3) & 1) << 3;           // k half
#pragma unroll
            for (int pr = 0; pr < 2; pr++) {
                uint32_t off = ((wn + pr * 16 + bln) * GP + k16 + blk) * 2;
                ldmx4(bh[pr], sBh + off);
                ldmx4(bl[pr], sBl + off);
            }
            const uint32_t arow = lane & 15;
            const uint32_t acol = (lane >> 4) << 3;
#pragma unroll
            for (int mt = 0; mt < 4; mt++) {
                uint32_t ah[4], al[4];
                uint32_t off = ((wm + mt * 16 + arow) * GP + k16 + acol) * 2;
                ldmx4(ah, sAh + off);
                ldmx4(al, sAl + off);
#pragma unroll
                for (int nt = 0; nt < 4; nt++) {
                    uint32_t b0h = bh[nt >> 1][(nt & 1) * 2];
                    uint32_t b1h = bh[nt >> 1][(nt & 1) * 2 + 1];
                    uint32_t b0l = bl[nt >> 1][(nt & 1) * 2];
                    uint32_t b1l = bl[nt >> 1][(nt & 1) * 2 + 1];
                    mma16816(acc[mt][nt], ah, b0h, b1h);
                    mma16816(acc[mt][nt], ah, b0l, b1l);
                    mma16816(acc[mt][nt], al, b0h, b1h);
                }
            }
        }
    }

    // ---- epilogue: fragment -> gmem (float2 per half-frag) + bias ----
#pragma unroll
    for (int mt = 0; mt < 4; mt++) {
#pragma unroll
        for (int nt = 0; nt < 4; nt++) {
            int row = row0 + wm + mt * 16 + (lane >> 2);
            int col = col0 + wn + nt * 8 + (lane & 3) * 2;
            float2 bz = *(const float2*)&bias[col];
            *(float2*)(C + (size_t)row * N + col) =
                make_float2(acc[mt][nt][0] + bz.x, acc[mt][nt][1] + bz.y);
            *(float2*)(C + (size_t)(row + 8) * N + col) =
                make_float2(acc[mt][nt][2] + bz.x, acc[mt][nt][3] + bz.y);
        }
    }
}

// ---------------------------------------------------------------------------
// RoPE + split/transpose (unchanged; fp64 angles track reference precision)
// ---------------------------------------------------------------------------
__global__ void rope_split_kernel()
{
    int idx = blockIdx.x * 256 + threadIdx.x;
    int d = idx & (HDIM - 1);
    int h = (idx >> 6) & (NHEADS - 1);
    int s = (idx >> 10) & (SS - 1);
    int b = idx >> 21;
    const float* base = g_qkv + (size_t)(b * SS + s) * (3 * D_MODEL);
    int off = h * HDIM;
    int dp = d & (HALF - 1);
    double inv = pow(10000.0, -((double)dp) / (double)HALF);
    double ang = (double)s * inv;
    double csd, snd;
    sincos(ang, &snd, &csd);
    float cs = (float)csd, sn = (float)snd;
    float q1 = base[off + dp],            q2 = base[off + dp + HALF];
    float k1 = base[D_MODEL + off + dp],  k2 = base[D_MODEL + off + dp + HALF];
    float qo, ko;
    if (d < HALF) { qo = q1 * cs - q2 * sn; ko = k1 * cs - k2 * sn; }
    else          { qo = q1 * sn + q2 * cs; ko = k1 * sn + k2 * cs; }
    int o = ((b * NHEADS + h) * SS + s) * HDIM + d;
    g_q[o] = qo;
    g_k[o] = ko;
    g_v[o] = base[2 * D_MODEL + off + d];
}

// ---------------------------------------------------------------------------
// Flash attention v2 (unchanged): 64x64 tile, 4x4 microtile, fp32.
// ---------------------------------------------------------------------------
__global__ void __launch_bounds__(256)
flash_attn_kernel()
{
    __shared__ float Qs[64][64];
    __shared__ float KP[64][64];
    __shared__ float Vs[64][64];

    const int tid = threadIdx.x;
    const int ty  = tid >> 4;
    const int tx  = tid & 15;
    const int bh  = blockIdx.y;
    const int q0  = blockIdx.x * 64;

    const float* Qb = g_q + (size_t)bh * SS * HDIM;
    const float* Kb = g_k + (size_t)bh * SS * HDIM;
    const float* Vb = g_v + (size_t)bh * SS * HDIM;

#pragma unroll
    for (int i = 0; i < 4; i++) {
        int j  = tid + i * 256;
        int qr = j >> 4, dq = (j & 15) << 2;
        float4 v = *(const float4*)(Qb + (size_t)(q0 + qr) * HDIM + dq);
        v.x *= 0.125f; v.y *= 0.125f; v.z *= 0.125f; v.w *= 0.125f;
        *(float4*)&Qs[qr][dq] = v;
    }

    float o[16];
#pragma unroll
    for (int j = 0; j < 16; j++) o[j] = 0.f;
    float mrow[4], lrow[4];
#pragma unroll
    for (int i = 0; i < 4; i++) { mrow[i] = -INFINITY; lrow[i] = 0.f; }

    for (int kt = 0; kt <= (int)blockIdx.x; kt++) {
        const int k0 = kt * 64;
        __syncthreads();
#pragma unroll
        for (int i = 0; i < 4; i++) {
            int j  = tid + i * 256;
            int kq = j & 63, d4 = (j >> 6) << 2;
            float4 kv = *(const float4*)(Kb + (size_t)(k0 + kq) * HDIM + d4);
            KP[d4 + 0][kq] = kv.x; KP[d4 + 1][kq] = kv.y;
            KP[d4 + 2][kq] = kv.z; KP[d4 + 3][kq] = kv.w;
            int key = j >> 4, dq = (j & 15) << 2;
            *(float4*)&Vs[key][dq] =
                *(const float4*)(Vb + (size_t)(k0 + key) * HDIM + dq);
        }
        __syncthreads();

        float sc[16];
#pragma unroll
        for (int j = 0; j < 16; j++) sc[j] = 0.f;
#pragma unroll 2
        for (int d0 = 0; d0 < HDIM; d0 += 4) {
            float4 q4[4], k4[4];
#pragma unroll
            for (int i = 0; i < 4; i++) q4[i] = *(const float4*)&Qs[ty * 4 + i][d0];
#pragma unroll
            for (int t = 0; t < 4; t++) k4[t] = *(const float4*)&KP[d0 + t][tx * 4];
#pragma unroll
            for (int i = 0; i < 4; i++) {
                float qa0 = q4[i].x, qa1 = q4[i].y, qa2 = q4[i].z, qa3 = q4[i].w;
                sc[i*4+0] += qa0*k4[0].x + qa1*k4[1].x + qa2*k4[2].x + qa3*k4[3].x;
                sc[i*4+1] += qa0*k4[0].y + qa1*k4[1].y + qa2*k4[2].y + qa3*k4[3].y;
                sc[i*4+2] += qa0*k4[0].z + qa1*k4[1].z + qa2*k4[2].z + qa3*k4[3].z;
                sc[i*4+3] += qa0*k4[0].w + qa1*k4[1].w + qa2*k4[2].w + qa3*k4[3].w;
            }
        }

        if (kt == (int)blockIdx.x) {
#pragma unroll
            for (int i = 0; i < 4; i++)
#pragma unroll
                for (int jj = 0; jj < 4; jj++)
                    if (k0 + tx * 4 + jj > q0 + ty * 4 + i)
                        sc[i * 4 + jj] = -INFINITY;
        }

#pragma unroll
        for (int i = 0; i < 4; i++) {
            float mx = fmaxf(fmaxf(sc[i*4+0], sc[i*4+1]),
                             fmaxf(sc[i*4+2], sc[i*4+3]));
            mx = fmaxf(mx, __shfl_xor_sync(0xffffffffu, mx, 1));
            mx = fmaxf(mx, __shfl_xor_sync(0xffffffffu, mx, 2));
            mx = fmaxf(mx, __shfl_xor_sync(0xffffffffu, mx, 4));
            mx = fmaxf(mx, __shfl_xor_sync(0xffffffffu, mx, 8));
            float mn    = fmaxf(mrow[i], mx);
            float alpha = __expf(mrow[i] - mn);
            float ls = 0.f;
#pragma unroll
            for (int jj = 0; jj < 4; jj++) {
                float p = __expf(sc[i * 4 + jj] - mn);
                sc[i * 4 + jj] = p;
                ls += p;
            }
            ls += __shfl_xor_sync(0xffffffffu, ls, 1);
            ls += __shfl_xor_sync(0xffffffffu, ls, 2);
            ls += __shfl_xor_sync(0xffffffffu, ls, 4);
            ls += __shfl_xor_sync(0xffffffffu, ls, 8);
            lrow[i] = lrow[i] * alpha + ls;
            mrow[i] = mn;
#pragma unroll
            for (int jj = 0; jj < 4; jj++) o[i * 4 + jj] *= alpha;
        }

        __syncthreads();
#pragma unroll
        for (int i = 0; i < 4; i++)
            *(float4*)&KP[ty * 4 + i][tx * 4] =
                make_float4(sc[i*4+0], sc[i*4+1], sc[i*4+2], sc[i*4+3]);
        __syncthreads();

#pragma unroll 2
        for (int kp = 0; kp < 64; kp += 4) {
            float4 p4[4], v4[4];
#pragma unroll
            for (int i = 0; i < 4; i++) p4[i] = *(const float4*)&KP[ty * 4 + i][kp];
#pragma unroll
            for (int t = 0; t < 4; t++) v4[t] = *(const float4*)&Vs[kp + t][tx * 4];
#pragma unroll
            for (int i = 0; i < 4; i++) {
                float pa0 = p4[i].x, pa1 = p4[i].y, pa2 = p4[i].z, pa3 = p4[i].w;
                o[i*4+0] += pa0*v4[0].x + pa1*v4[1].x + pa2*v4[2].x + pa3*v4[3].x;
                o[i*4+1] += pa0*v4[0].y + pa1*v4[1].y + pa2*v4[2].y + pa3*v4[3].y;
                o[i*4+2] += pa0*v4[0].z + pa1*v4[1].z + pa2*v4[2].z + pa3*v4[3].z;
                o[i*4+3] += pa0*v4[0].w + pa1*v4[1].w + pa2*v4[2].w + pa3*v4[3].w;
            }
        }
    }

    const int b = bh >> 4, h = bh & 15;
#pragma unroll
    for (int i = 0; i < 4; i++) {
        float invl = 1.f / lrow[i];
        int row = q0 + ty * 4 + i;
        float* outp = g_attn + (size_t)(b * SS + row) * D_MODEL + h * HDIM + tx * 4;
        *(float4*)outp = make_float4(o[i*4+0] * invl, o[i*4+1] * invl,
                                     o[i*4+2] * invl, o[i*4+3] * invl);
    }
}

// ---------------------------------------------------------------------------
extern "C" void kernel_launch(void* const* d_in, const int* in_sizes, int n_in,
                              void* d_out, int out_size)
{
    // Resolve inputs BY ELEMENT COUNT (pairwise distinct sizes).
    const float* x     = 0;
    const float* qkv_w = 0;
    const float* qkv_b = 0;
    const float* out_w = 0;
    const float* out_b = 0;
    for (int i = 0; i < n_in; i++) {
        switch (in_sizes[i]) {
            case MTOK * D_MODEL:            x     = (const float*)d_in[i]; break;
            case 3 * D_MODEL * D_MODEL:     qkv_w = (const float*)d_in[i]; break;
            case 3 * D_MODEL:               qkv_b = (const float*)d_in[i]; break;
            case D_MODEL * D_MODEL:         out_w = (const float*)d_in[i]; break;
            case D_MODEL:                   out_b = (const float*)d_in[i]; break;
            default: break;
        }
    }
    float* out = (float*)d_out;

    float *qkv_p, *attn_p;
    cudaGetSymbolAddress((void**)&qkv_p,  g_qkv);
    cudaGetSymbolAddress((void**)&attn_p, g_attn);

    // 1) QKV projection (HMMA split-bf16)
    gemm_mma<<<dim3((3 * D_MODEL) / 128, MTOK / 128), 256>>>(
        x, qkv_w, qkv_b, qkv_p, MTOK, 3 * D_MODEL, D_MODEL);

    // 2) RoPE + split
    rope_split_kernel<<<(MTOK * D_MODEL) / 256, 256>>>();

    // 3) causal flash attention (fp32)
    flash_attn_kernel<<<dim3(SS / 64, BB * NHEADS), 256>>>();

    // 4) output projection (HMMA split-bf16)
    gemm_mma<<<dim3(D_MODEL / 128, MTOK / 128), 256>>>(
        attn_p, out_w, out_b, out, MTOK, D_MODEL, D_MODEL);
}

// round 7
// speedup vs baseline: 7.5403x; 3.1689x over previous
#include <cuda_runtime.h>
#include <cuda_bf16.h>
#include <math.h>
#include <stdint.h>

#define D_MODEL 1024
#define NHEADS  16
#define HDIM    64
#define HALF    32
#define BB      2
#define SS      2048
#define MTOK    (BB*SS)          // 4096 tokens

// Scratch (static __device__ arrays — no allocations allowed)
__device__ float g_qkv[MTOK * 3 * D_MODEL];   // [4096][3072]
__device__ float g_q[MTOK * D_MODEL];         // [B*H][S][64]
__device__ float g_k[MTOK * D_MODEL];
__device__ float g_v[MTOK * D_MODEL];
__device__ float g_attn[MTOK * D_MODEL];      // [4096][1024]
__device__ float g_ropet[SS * HALF * 2];      // cos/sin table

// ===========================================================================
// Warp-level MMA helpers (compute_103-baseline PTX: ldmatrix + mma.sync bf16)
// ===========================================================================
__device__ __forceinline__ uint32_t smem_u32(const void* p) {
    uint32_t a;
    asm("{ .reg .u64 t; cvta.to.shared.u64 t, %1; cvt.u32.u64 %0, t; }"
        : "=r"(a) : "l"(p));
    return a;
}
__device__ __forceinline__ void ldmx4(uint32_t* r, uint32_t addr) {
    asm volatile("ldmatrix.sync.aligned.m8n8.x4.shared.b16 {%0,%1,%2,%3}, [%4];"
                 : "=r"(r[0]), "=r"(r[1]), "=r"(r[2]), "=r"(r[3]) : "r"(addr));
}
__device__ __forceinline__ void ldmx4t(uint32_t* r, uint32_t addr) {
    asm volatile("ldmatrix.sync.aligned.m8n8.x4.trans.shared.b16 {%0,%1,%2,%3}, [%4];"
                 : "=r"(r[0]), "=r"(r[1]), "=r"(r[2]), "=r"(r[3]) : "r"(addr));
}
__device__ __forceinline__ void mma16816(float* c, const uint32_t* a,
                                         uint32_t b0, uint32_t b1) {
    asm volatile(
        "mma.sync.aligned.m16n8k16.row.col.f32.bf16.bf16.f32 "
        "{%0,%1,%2,%3}, {%4,%5,%6,%7}, {%8,%9}, {%0,%1,%2,%3};"
        : "+f"(c[0]), "+f"(c[1]), "+f"(c[2]), "+f"(c[3])
        : "r"(a[0]), "r"(a[1]), "r"(a[2]), "r"(a[3]), "r"(b0), "r"(b1));
}
__device__ __forceinline__ uint32_t pack_hi(float x, float y,
                                            float& rx, float& ry) {
    __nv_bfloat16 hx = __float2bfloat16(x);
    __nv_bfloat16 hy = __float2bfloat16(y);
    rx = x - __bfloat162float(hx);
    ry = y - __bfloat162float(hy);
    return ((uint32_t)__bfloat16_as_ushort(hy) << 16) |
           (uint32_t)__bfloat16_as_ushort(hx);
}
__device__ __forceinline__ uint32_t pack_bf(float x, float y) {
    return ((uint32_t)__bfloat16_as_ushort(__float2bfloat16(y)) << 16) |
           (uint32_t)__bfloat16_as_ushort(__float2bfloat16(x));
}

// ===========================================================================
// HMMA split-bf16 GEMM (unchanged from round 6): C = A @ W^T + bias
// ===========================================================================
#define GP 40   // smem pitch in bf16

__global__ void __launch_bounds__(256, 2)
gemm_mma(const float* __restrict__ A, const float* __restrict__ W,
         const float* __restrict__ bias, float* __restrict__ C,
         int M, int N, int K)
{
    __shared__ __align__(16) __nv_bfloat16 Ah[128 * GP];
    __shared__ __align__(16) __nv_bfloat16 Al[128 * GP];
    __shared__ __align__(16) __nv_bfloat16 Bh[128 * GP];
    __shared__ __align__(16) __nv_bfloat16 Bl[128 * GP];

    const int tid  = threadIdx.x;
    const int wid  = tid >> 5;
    const int lane = tid & 31;
    const int row0 = blockIdx.y * 128;
    const int col0 = blockIdx.x * 128;
    const int wm   = (wid >> 2) * 64;
    const int wn   = (wid & 3) * 32;

    const uint32_t sAh = smem_u32(Ah), sAl = smem_u32(Al);
    const uint32_t sBh = smem_u32(Bh), sBl = smem_u32(Bl);

    float acc[4][4][4];
#pragma unroll
    for (int mt = 0; mt < 4; mt++)
#pragma unroll
        for (int nt = 0; nt < 4; nt++)
#pragma unroll
            for (int e = 0; e < 4; e++) acc[mt][nt][e] = 0.f;

    const int fr = tid >> 3;
    const int fc = (tid & 7) << 2;

    for (int k0 = 0; k0 < K; k0 += 32) {
        __syncthreads();
#pragma unroll
        for (int i = 0; i < 4; i++) {
            int r = fr + i * 32;
            float4 a4 = *(const float4*)(A + (size_t)(row0 + r) * K + k0 + fc);
            float lx, ly, lz, lw;
            uint32_t h01 = pack_hi(a4.x, a4.y, lx, ly);
            uint32_t h23 = pack_hi(a4.z, a4.w, lz, lw);
            *(uint2*)&Ah[r * GP + fc] = make_uint2(h01, h23);
            *(uint2*)&Al[r * GP + fc] = make_uint2(pack_bf(lx, ly), pack_bf(lz, lw));

            float4 b4 = *(const float4*)(W + (size_t)(col0 + r) * K + k0 + fc);
            uint32_t g01 = pack_hi(b4.x, b4.y, lx, ly);
            uint32_t g23 = pack_hi(b4.z, b4.w, lz, lw);
            *(uint2*)&Bh[r * GP + fc] = make_uint2(g01, g23);
            *(uint2*)&Bl[r * GP + fc] = make_uint2(pack_bf(lx, ly), pack_bf(lz, lw));
        }
        __syncthreads();

#pragma unroll
        for (int k16 = 0; k16 < 32; k16 += 16) {
            uint32_t bh[2][4], bl[2][4];
            const uint32_t bln = (lane & 7) + ((lane >> 4) << 3);
            const uint32_t blk = ((lane >> 3) & 1) << 3;
#pragma unroll
            for (int pr = 0; pr < 2; pr++) {
                uint32_t off = ((wn + pr * 16 + bln) * GP + k16 + blk) * 2;
                ldmx4(bh[pr], sBh + off);
                ldmx4(bl[pr], sBl + off);
            }
            const uint32_t arow = lane & 15;
            const uint32_t acol = (lane >> 4) << 3;
#pragma unroll
            for (int mt = 0; mt < 4; mt++) {
                uint32_t ah[4], al[4];
                uint32_t off = ((wm + mt * 16 + arow) * GP + k16 + acol) * 2;
                ldmx4(ah, sAh + off);
                ldmx4(al, sAl + off);
#pragma unroll
                for (int nt = 0; nt < 4; nt++) {
                    uint32_t b0h = bh[nt >> 1][(nt & 1) * 2];
                    uint32_t b1h = bh[nt >> 1][(nt & 1) * 2 + 1];
                    uint32_t b0l = bl[nt >> 1][(nt & 1) * 2];
                    uint32_t b1l = bl[nt >> 1][(nt & 1) * 2 + 1];
                    mma16816(acc[mt][nt], ah, b0h, b1h);
                    mma16816(acc[mt][nt], ah, b0l, b1l);
                    mma16816(acc[mt][nt], al, b0h, b1h);
                }
            }
        }
    }

#pragma unroll
    for (int mt = 0; mt < 4; mt++) {
#pragma unroll
        for (int nt = 0; nt < 4; nt++) {
            int row = row0 + wm + mt * 16 + (lane >> 2);
            int col = col0 + wn + nt * 8 + (lane & 3) * 2;
            float2 bz = *(const float2*)&bias[col];
            *(float2*)(C + (size_t)row * N + col) =
                make_float2(acc[mt][nt][0] + bz.x, acc[mt][nt][1] + bz.y);
            *(float2*)(C + (size_t)(row + 8) * N + col) =
                make_float2(acc[mt][nt][2] + bz.x, acc[mt][nt][3] + bz.y);
        }
    }
}

// ---------------------------------------------------------------------------
// RoPE: fp64 trig table (2048 x 32) computed once per launch, then fp32 apply.
// ---------------------------------------------------------------------------
__global__ void rope_table_kernel()
{
    int idx = blockIdx.x * 256 + threadIdx.x;   // 0..65535
    int s  = idx >> 5;
    int dp = idx & 31;
    double inv = pow(10000.0, -((double)dp) / (double)HALF);
    double snd, csd;
    sincos((double)s * inv, &snd, &csd);
    g_ropet[idx * 2 + 0] = (float)csd;
    g_ropet[idx * 2 + 1] = (float)snd;
}

__global__ void rope_split_kernel()
{
    int idx = blockIdx.x * 256 + threadIdx.x;
    int d = idx & (HDIM - 1);
    int h = (idx >> 6) & (NHEADS - 1);
    int s = (idx >> 10) & (SS - 1);
    int b = idx >> 21;
    const float* base = g_qkv + (size_t)(b * SS + s) * (3 * D_MODEL);
    int off = h * HDIM;
    int dp = d & (HALF - 1);
    float cs = g_ropet[(s * HALF + dp) * 2 + 0];
    float sn = g_ropet[(s * HALF + dp) * 2 + 1];
    float q1 = base[off + dp],            q2 = base[off + dp + HALF];
    float k1 = base[D_MODEL + off + dp],  k2 = base[D_MODEL + off + dp + HALF];
    float qo, ko;
    if (d < HALF) { qo = q1 * cs - q2 * sn; ko = k1 * cs - k2 * sn; }
    else          { qo = q1 * sn + q2 * cs; ko = k1 * sn + k2 * cs; }
    int o = ((b * NHEADS + h) * SS + s) * HDIM + d;
    g_q[o] = qo;
    g_k[o] = ko;
    g_v[o] = base[2 * D_MODEL + off + d];
}

// ===========================================================================
// Flash attention v3: HMMA split-bf16. 64q x 64k tiles, 128 threads (4 warps),
// warp owns m16 rows. K/V smem [key][d] pitch 72; V b-frags via ldmatrix.trans.
// ===========================================================================
#define FP 72   // flash smem pitch in bf16
#define SQH 0
#define SQL (64*FP)
#define SKH (2*64*FP)
#define SKL (3*64*FP)
#define SVH (4*64*FP)
#define SVL (5*64*FP)
#define FSMEM (6*64*FP*2)    // 55296 bytes

__global__ void __launch_bounds__(128)
flash_mma_kernel()
{
    extern __shared__ __nv_bfloat16 fsm[];
    const uint32_t smb = smem_u32(fsm);
    const int tid  = threadIdx.x;
    const int wid  = tid >> 5;
    const int lane = tid & 31;
    const int bh   = blockIdx.y;
    const int qb   = blockIdx.x;
    const int q0   = qb * 64;
    const int wm   = wid * 16;           // warp's query-row offset in tile

    const float* Qb = g_q + (size_t)bh * SS * HDIM;
    const float* Kb = g_k + (size_t)bh * SS * HDIM;
    const float* Vb = g_v + (size_t)bh * SS * HDIM;

    // fill coordinates: 1024 float4 slots over 128 threads
    const int fr = 0;  (void)fr;

    // ---- Q fill (scaled by 1/8, split hi/lo) ----
#pragma unroll
    for (int i = 0; i < 8; i++) {
        int idx = tid + i * 128;
        int r = idx >> 4, c4 = (idx & 15) << 2;
        float4 q4 = *(const float4*)(Qb + (size_t)(q0 + r) * HDIM + c4);
        q4.x *= 0.125f; q4.y *= 0.125f; q4.z *= 0.125f; q4.w *= 0.125f;
        float lx, ly, lz, lw;
        uint32_t h01 = pack_hi(q4.x, q4.y, lx, ly);
        uint32_t h23 = pack_hi(q4.z, q4.w, lz, lw);
        *(uint2*)&fsm[SQH + r * FP + c4] = make_uint2(h01, h23);
        *(uint2*)&fsm[SQL + r * FP + c4] = make_uint2(pack_bf(lx, ly), pack_bf(lz, lw));
    }
    __syncthreads();

    // ---- hoist Q a-frags (4 k16-steps, hi + lo) ----
    uint32_t qh[4][4], ql[4][4];
    {
        const uint32_t arow = lane & 15;
        const uint32_t acol = (lane >> 4) << 3;
#pragma unroll
        for (int ks = 0; ks < 4; ks++) {
            uint32_t off = ((wm + arow) * FP + ks * 16 + acol) * 2;
            ldmx4(qh[ks], smb + SQH * 2 + off);
            ldmx4(ql[ks], smb + SQL * 2 + off);
        }
    }

    float o[8][4];
#pragma unroll
    for (int nt = 0; nt < 8; nt++)
#pragma unroll
        for (int e = 0; e < 4; e++) o[nt][e] = 0.f;
    float mrun[2] = {-INFINITY, -INFINITY};
    float lrun[2] = {0.f, 0.f};

    const uint32_t bln = (lane & 7) + ((lane >> 4) << 3);
    const uint32_t blk = ((lane >> 3) & 1) << 3;
    // V trans-ldmatrix lane address components
    const uint32_t vrow = (lane & 7) + (((lane >> 3) & 1) << 3);  // key within 16
    const uint32_t vcol = (lane >> 4) << 3;                       // d offset within pair

    for (int kt = 0; kt <= qb; kt++) {
        const int k0 = kt * 64;
        __syncthreads();
        // ---- K/V fill (split hi/lo, natural [key][d]) ----
#pragma unroll
        for (int i = 0; i < 8; i++) {
            int idx = tid + i * 128;
            int r = idx >> 4, c4 = (idx & 15) << 2;
            float4 k4 = *(const float4*)(Kb + (size_t)(k0 + r) * HDIM + c4);
            float lx, ly, lz, lw;
            uint32_t h01 = pack_hi(k4.x, k4.y, lx, ly);
            uint32_t h23 = pack_hi(k4.z, k4.w, lz, lw);
            *(uint2*)&fsm[SKH + r * FP + c4] = make_uint2(h01, h23);
            *(uint2*)&fsm[SKL + r * FP + c4] = make_uint2(pack_bf(lx, ly), pack_bf(lz, lw));

            float4 v4 = *(const float4*)(Vb + (size_t)(k0 + r) * HDIM + c4);
            uint32_t g01 = pack_hi(v4.x, v4.y, lx, ly);
            uint32_t g23 = pack_hi(v4.z, v4.w, lz, lw);
            *(uint2*)&fsm[SVH + r * FP + c4] = make_uint2(g01, g23);
            *(uint2*)&fsm[SVL + r * FP + c4] = make_uint2(pack_bf(lx, ly), pack_bf(lz, lw));
        }
        __syncthreads();

        // ---- S = Q K^T (3-term split) ----
        float sc[8][4];
#pragma unroll
        for (int nt = 0; nt < 8; nt++)
#pragma unroll
            for (int e = 0; e < 4; e++) sc[nt][e] = 0.f;
#pragma unroll
        for (int ks = 0; ks < 4; ks++) {
#pragma unroll
            for (int pr = 0; pr < 4; pr++) {
                uint32_t kh[4], kl[4];
                uint32_t off = ((pr * 16 + bln) * FP + ks * 16 + blk) * 2;
                ldmx4(kh, smb + SKH * 2 + off);
                ldmx4(kl, smb + SKL * 2 + off);
                mma16816(sc[2*pr],   qh[ks], kh[0], kh[1]);
                mma16816(sc[2*pr],   qh[ks], kl[0], kl[1]);
                mma16816(sc[2*pr],   ql[ks], kh[0], kh[1]);
                mma16816(sc[2*pr+1], qh[ks], kh[2], kh[3]);
                mma16816(sc[2*pr+1], qh[ks], kl[2], kl[3]);
                mma16816(sc[2*pr+1], ql[ks], kh[2], kh[3]);
            }
        }

        // ---- causal mask on diagonal block ----
        if (kt == qb) {
            int row0g = q0 + wm + (lane >> 2);
#pragma unroll
            for (int nt = 0; nt < 8; nt++) {
                int colg = k0 + nt * 8 + (lane & 3) * 2;
                if (colg     > row0g)     sc[nt][0] = -INFINITY;
                if (colg + 1 > row0g)     sc[nt][1] = -INFINITY;
                if (colg     > row0g + 8) sc[nt][2] = -INFINITY;
                if (colg + 1 > row0g + 8) sc[nt][3] = -INFINITY;
            }
        }

        // ---- online softmax (2 rows per thread; reduce over lanes xor 1,2) ----
#pragma unroll
        for (int hrow = 0; hrow < 2; hrow++) {
            const int e0 = hrow * 2;
            float mx = -INFINITY;
#pragma unroll
            for (int nt = 0; nt < 8; nt++)
                mx = fmaxf(mx, fmaxf(sc[nt][e0], sc[nt][e0 + 1]));
            mx = fmaxf(mx, __shfl_xor_sync(0xffffffffu, mx, 1));
            mx = fmaxf(mx, __shfl_xor_sync(0xffffffffu, mx, 2));
            float mn    = fmaxf(mrun[hrow], mx);
            float alpha = __expf(mrun[hrow] - mn);
            float ls = 0.f;
#pragma unroll
            for (int nt = 0; nt < 8; nt++) {
                float p0 = __expf(sc[nt][e0]     - mn);
                float p1 = __expf(sc[nt][e0 + 1] - mn);
                sc[nt][e0] = p0; sc[nt][e0 + 1] = p1;
                ls += p0 + p1;
            }
            ls += __shfl_xor_sync(0xffffffffu, ls, 1);
            ls += __shfl_xor_sync(0xffffffffu, ls, 2);
            lrun[hrow] = lrun[hrow] * alpha + ls;
            mrun[hrow] = mn;
#pragma unroll
            for (int nt = 0; nt < 8; nt++) {
                o[nt][e0] *= alpha; o[nt][e0 + 1] *= alpha;
            }
        }

        // ---- O += P V (3-term split; P a-frags from S c-frags) ----
#pragma unroll
        for (int ks = 0; ks < 4; ks++) {
            // P fragments for keys [16ks, 16ks+16): ntiles 2ks, 2ks+1
            uint32_t pa[4], pl[4];
            {
                float l0, l1, l2, l3;
                pa[0] = pack_hi(sc[2*ks][0],   sc[2*ks][1],   l0, l1);
                pa[1] = pack_hi(sc[2*ks][2],   sc[2*ks][3],   l2, l3);
                pl[0] = pack_bf(l0, l1);
                pl[1] = pack_bf(l2, l3);
                pa[2] = pack_hi(sc[2*ks+1][0], sc[2*ks+1][1], l0, l1);
                pa[3] = pack_hi(sc[2*ks+1][2], sc[2*ks+1][3], l2, l3);
                pl[2] = pack_bf(l0, l1);
                pl[3] = pack_bf(l2, l3);
            }
#pragma unroll
            for (int dp = 0; dp < 4; dp++) {
                uint32_t vh[4], vl[4];
                uint32_t off = ((ks * 16 + vrow) * FP + dp * 16 + vcol) * 2;
                ldmx4t(vh, smb + SVH * 2 + off);
                ldmx4t(vl, smb + SVL * 2 + off);
                mma16816(o[2*dp],   pa, vh[0], vh[1]);
                mma16816(o[2*dp],   pa, vl[0], vl[1]);
                mma16816(o[2*dp],   pl, vh[0], vh[1]);
                mma16816(o[2*dp+1], pa, vh[2], vh[3]);
                mma16816(o[2*dp+1], pa, vl[2], vl[3]);
                mma16816(o[2*dp+1], pl, vh[2], vh[3]);
            }
        }
    }

    // ---- epilogue: normalize, scatter c-frags to g_attn [b*S+q][h*64+d] ----
    const int b = bh >> 4, h = bh & 15;
    const float inv0 = 1.f / lrun[0];
    const float inv1 = 1.f / lrun[1];
    int row0g = q0 + wm + (lane >> 2);
#pragma unroll
    for (int nt = 0; nt < 8; nt++) {
        int col = h * HDIM + nt * 8 + (lane & 3) * 2;
        *(float2*)(g_attn + (size_t)(b * SS + row0g) * D_MODEL + col) =
            make_float2(o[nt][0] * inv0, o[nt][1] * inv0);
        *(float2*)(g_attn + (size_t)(b * SS + row0g + 8) * D_MODEL + col) =
            make_float2(o[nt][2] * inv1, o[nt][3] * inv1);
    }
}

// ---------------------------------------------------------------------------
extern "C" void kernel_launch(void* const* d_in, const int* in_sizes, int n_in,
                              void* d_out, int out_size)
{
    // Resolve inputs BY ELEMENT COUNT (pairwise distinct sizes).
    const float* x     = 0;
    const float* qkv_w = 0;
    const float* qkv_b = 0;
    const float* out_w = 0;
    const float* out_b = 0;
    for (int i = 0; i < n_in; i++) {
        switch (in_sizes[i]) {
            case MTOK * D_MODEL:            x     = (const float*)d_in[i]; break;
            case 3 * D_MODEL * D_MODEL:     qkv_w = (const float*)d_in[i]; break;
            case 3 * D_MODEL:               qkv_b = (const float*)d_in[i]; break;
            case D_MODEL * D_MODEL:         out_w = (const float*)d_in[i]; break;
            case D_MODEL:                   out_b = (const float*)d_in[i]; break;
            default: break;
        }
    }
    float* out = (float*)d_out;

    float *qkv_p, *attn_p;
    cudaGetSymbolAddress((void**)&qkv_p,  g_qkv);
    cudaGetSymbolAddress((void**)&attn_p, g_attn);

    cudaFuncSetAttribute(flash_mma_kernel,
                         cudaFuncAttributeMaxDynamicSharedMemorySize, FSMEM);

    // 1) QKV projection (HMMA split-bf16)
    gemm_mma<<<dim3((3 * D_MODEL) / 128, MTOK / 128), 256>>>(
        x, qkv_w, qkv_b, qkv_p, MTOK, 3 * D_MODEL, D_MODEL);

    // 2) RoPE table + apply
    rope_table_kernel<<<SS * HALF / 256, 256>>>();
    rope_split_kernel<<<(MTOK * D_MODEL) / 256, 256>>>();

    // 3) causal flash attention (HMMA split-bf16)
    flash_mma_kernel<<<dim3(SS / 64, BB * NHEADS), 128, FSMEM>>>();

    // 4) output projection (HMMA split-bf16)
    gemm_mma<<<dim3(D_MODEL / 128, MTOK / 128), 256>>>(
        attn_p, out_w, out_b, out, MTOK, D_MODEL, D_MODEL);
}